// round 2
// baseline (speedup 1.0000x reference)
#include <cuda_runtime.h>
#include <cstdint>

#define NROWS 8192
#define DIN   2048
#define DOUT  2048

#define BM 128
#define BN 128
#define BK 64
#define ASTRIDE (BK + 16)   // 80 bytes, multiple of 16 for uint4 stores
#define BSTRIDE (BK + 16)

// Device scratch (allocation-free): quantized activations + repacked weights
__device__ uint8_t g_xq[(size_t)NROWS * DIN];   // 16 MB
__device__ uint8_t g_wq[(size_t)DIN * DOUT];    //  4 MB

// ---------------------------------------------------------------------------
// Kernel 0: repack weights int32 (0..255 per word) -> u8
// ---------------------------------------------------------------------------
__global__ void repack_w_kernel(const int* __restrict__ w32)
{
    int i = blockIdx.x * blockDim.x + threadIdx.x;   // one u32 (4 weights) per thread
    const int total = (DIN * DOUT) / 4;
    if (i >= total) return;
    int4 v = reinterpret_cast<const int4*>(w32)[i];
    uint32_t packed = ((uint32_t)v.x & 0xFF)
                    | (((uint32_t)v.y & 0xFF) << 8)
                    | (((uint32_t)v.z & 0xFF) << 16)
                    | (((uint32_t)v.w & 0xFF) << 24);
    reinterpret_cast<uint32_t*>(g_wq)[i] = packed;
}

// ---------------------------------------------------------------------------
// Kernel 1: quantize x (f32) -> u8
// xq = trunc(clip(rint(x/scale) + zp, 0, 255))  — matches jnp exactly
// ---------------------------------------------------------------------------
__global__ void quant_kernel(const float* __restrict__ x,
                             const float* __restrict__ scale_p,
                             const float* __restrict__ zp_p)
{
    const float scale = __ldg(scale_p);
    const float zp    = __ldg(zp_p);
    int i = blockIdx.x * blockDim.x + threadIdx.x;
    const int total = (NROWS * DIN) / 4;
    if (i >= total) return;

    float4 v = reinterpret_cast<const float4*>(x)[i];

    uint32_t q0 = (uint32_t)fminf(fmaxf(rintf(__fdiv_rn(v.x, scale)) + zp, 0.0f), 255.0f);
    uint32_t q1 = (uint32_t)fminf(fmaxf(rintf(__fdiv_rn(v.y, scale)) + zp, 0.0f), 255.0f);
    uint32_t q2 = (uint32_t)fminf(fmaxf(rintf(__fdiv_rn(v.z, scale)) + zp, 0.0f), 255.0f);
    uint32_t q3 = (uint32_t)fminf(fmaxf(rintf(__fdiv_rn(v.w, scale)) + zp, 0.0f), 255.0f);

    reinterpret_cast<uint32_t*>(g_xq)[i] = q0 | (q1 << 8) | (q2 << 16) | (q3 << 24);
}

// ---------------------------------------------------------------------------
// Kernel 2: u8 x u8 GEMM via mma.sync.m16n8k32 (s32 accum), fused epilogue:
//   out = (((acc + bias) & 0xFFFF) - zp) * scale
// ---------------------------------------------------------------------------
__device__ __forceinline__ void mma_u8(int c[4], const uint32_t a[4], const uint32_t b[2])
{
    asm volatile(
        "mma.sync.aligned.m16n8k32.row.col.s32.u8.u8.s32 "
        "{%0,%1,%2,%3}, {%4,%5,%6,%7}, {%8,%9}, {%0,%1,%2,%3};\n"
        : "+r"(c[0]), "+r"(c[1]), "+r"(c[2]), "+r"(c[3])
        : "r"(a[0]), "r"(a[1]), "r"(a[2]), "r"(a[3]), "r"(b[0]), "r"(b[1]));
}

__global__ __launch_bounds__(256) void gemm_kernel(
    const int*   __restrict__ bias,     // [DOUT], int32-encoded uint16
    const float* __restrict__ scale_p,
    const float* __restrict__ zp_p,
    float*       __restrict__ out)      // [NROWS][DOUT]
{
    __shared__ uint8_t As[BM * ASTRIDE];   // row-major [m][k]
    __shared__ uint8_t Bs[BN * BSTRIDE];   // transposed [n][k]

    const int tid  = threadIdx.x;
    const int warp = tid >> 5;
    const int lane = tid & 31;
    const int warp_m = warp >> 2;   // 0..1  -> 64-row slab
    const int warp_n = warp & 3;    // 0..3  -> 32-col slab
    const int block_row = blockIdx.y * BM;
    const int block_col = blockIdx.x * BN;

    int acc[4][4][4];
    #pragma unroll
    for (int mi = 0; mi < 4; mi++)
        #pragma unroll
        for (int ni = 0; ni < 4; ni++)
            #pragma unroll
            for (int r = 0; r < 4; r++)
                acc[mi][ni][r] = 0;

    const int lrow = lane >> 2;       // 0..7
    const int lcol = lane & 3;        // 0..3

    for (int kt = 0; kt < DIN; kt += BK) {
        // ---- load A tile: 128 rows x 64 bytes = 512 uint4, 2 per thread ----
        #pragma unroll
        for (int r = 0; r < 2; r++) {
            int idx = r * 256 + tid;          // 0..511
            int arow = idx >> 2;              // 0..127
            int acol = idx & 3;               // 0..3 (x16 bytes)
            uint4 v = *reinterpret_cast<const uint4*>(
                g_xq + (size_t)(block_row + arow) * DIN + kt + acol * 16);
            *reinterpret_cast<uint4*>(As + arow * ASTRIDE + acol * 16) = v;
        }
        // ---- load B tile: 64 k-rows x 128 n-bytes, transpose to Bs[n][k] ----
        #pragma unroll
        for (int r = 0; r < 2; r++) {
            int idx = r * 256 + tid;          // 0..511
            int krow = idx >> 3;              // 0..63
            int n16  = idx & 7;               // 0..7 (x16 n's)
            uint4 v = *reinterpret_cast<const uint4*>(
                g_wq + (size_t)(kt + krow) * DOUT + block_col + n16 * 16);
            uint32_t w[4] = {v.x, v.y, v.z, v.w};
            #pragma unroll
            for (int j = 0; j < 4; j++)
                #pragma unroll
                for (int b = 0; b < 4; b++)
                    Bs[(n16 * 16 + j * 4 + b) * BSTRIDE + krow] =
                        (uint8_t)(w[j] >> (8 * b));
        }
        __syncthreads();

        // ---- compute: 2 k-steps of 32 ----
        #pragma unroll
        for (int kk = 0; kk < 2; kk++) {
            const int kb = kk * 32;
            uint32_t afr[4][4], bfr[4][2];
            #pragma unroll
            for (int mi = 0; mi < 4; mi++) {
                int row = warp_m * 64 + mi * 16 + lrow;
                const uint32_t* p  = reinterpret_cast<const uint32_t*>(
                    As + row * ASTRIDE + kb + lcol * 4);
                const uint32_t* p8 = reinterpret_cast<const uint32_t*>(
                    As + (row + 8) * ASTRIDE + kb + lcol * 4);
                afr[mi][0] = p[0];      // (row,   k 0-15)
                afr[mi][1] = p8[0];     // (row+8, k 0-15)
                afr[mi][2] = p[4];      // (row,   k 16-31)
                afr[mi][3] = p8[4];     // (row+8, k 16-31)
            }
            #pragma unroll
            for (int ni = 0; ni < 4; ni++) {
                int n = warp_n * 32 + ni * 8 + lrow;
                const uint32_t* p = reinterpret_cast<const uint32_t*>(
                    Bs + n * BSTRIDE + kb + lcol * 4);
                bfr[ni][0] = p[0];      // (k 0-15,  n)
                bfr[ni][1] = p[4];      // (k 16-31, n)
            }
            #pragma unroll
            for (int mi = 0; mi < 4; mi++)
                #pragma unroll
                for (int ni = 0; ni < 4; ni++)
                    mma_u8(acc[mi][ni], afr[mi], bfr[ni]);
        }
        __syncthreads();
    }

    // ---- epilogue: add bias, wrap to uint16, dequantize ----
    const float scale = __ldg(scale_p);
    const float zp    = __ldg(zp_p);

    #pragma unroll
    for (int mi = 0; mi < 4; mi++) {
        int row0 = block_row + warp_m * 64 + mi * 16 + lrow;
        #pragma unroll
        for (int ni = 0; ni < 4; ni++) {
            int col = block_col + warp_n * 32 + ni * 8 + lcol * 2;
            uint32_t b0 = (uint32_t)bias[col]     & 0xFFFFu;
            uint32_t b1 = (uint32_t)bias[col + 1] & 0xFFFFu;

            uint32_t v00 = ((uint32_t)acc[mi][ni][0] + b0) & 0xFFFFu;
            uint32_t v01 = ((uint32_t)acc[mi][ni][1] + b1) & 0xFFFFu;
            uint32_t v10 = ((uint32_t)acc[mi][ni][2] + b0) & 0xFFFFu;
            uint32_t v11 = ((uint32_t)acc[mi][ni][3] + b1) & 0xFFFFu;

            float2 o0, o1;
            o0.x = ((float)v00 - zp) * scale;
            o0.y = ((float)v01 - zp) * scale;
            o1.x = ((float)v10 - zp) * scale;
            o1.y = ((float)v11 - zp) * scale;

            *reinterpret_cast<float2*>(out + (size_t)row0 * DOUT + col) = o0;
            *reinterpret_cast<float2*>(out + (size_t)(row0 + 8) * DOUT + col) = o1;
        }
    }
}

// ---------------------------------------------------------------------------
extern "C" void kernel_launch(void* const* d_in, const int* in_sizes, int n_in,
                              void* d_out, int out_size)
{
    const float* x     = (const float*)d_in[0];
    const float* scale = (const float*)d_in[1];
    const float* zp    = (const float*)d_in[2];
    const int*   qk    = (const int*)d_in[3];   // int32-encoded uint8
    const int*   qb    = (const int*)d_in[4];   // int32-encoded uint16
    float* out = (float*)d_out;

    const int wtotal4 = (DIN * DOUT) / 4;
    repack_w_kernel<<<(wtotal4 + 255) / 256, 256>>>(qk);

    const int total4 = (NROWS * DIN) / 4;
    quant_kernel<<<(total4 + 255) / 256, 256>>>(x, scale, zp);

    dim3 grid(DOUT / BN, NROWS / BM);
    gemm_kernel<<<grid, 256>>>(qb, scale, zp, out);
}